// round 12
// baseline (speedup 1.0000x reference)
#include <cuda_runtime.h>
#include <cuda_bf16.h>
#include <cuda_fp16.h>

#define N_NODES 50000
#define E_EDGES 1600000
#define DIM     128
#define SLOTS   96      // max degree bucket capacity (Poisson(32): P(>96) ~ 1e-20)
#define CHUNK   12500   // 4-chunk agg1/gemm2 pipeline

// ---------------------------------------------------------------------------
// Scratch (device globals — no allocation allowed)
// Layer-1 GEMM writes g_h/g_hf; layer-2 GEMM writes g_h2/g_hf2 (no aliasing
// with agg1's gathers -> the chunk pipeline is race-free).
// ---------------------------------------------------------------------------
__device__ float  g_h  [N_NODES * DIM];       // layer-1 h (fp32)
__device__ __half g_hf [N_NODES * DIM];       // layer-1 h (fp16 gather copy)
__device__ float  g_h2 [N_NODES * DIM];       // layer-2 h (fp32)
__device__ __half g_hf2[N_NODES * DIM];       // layer-2 h (fp16 gather copy)
__device__ float  g_x1 [N_NODES * DIM];       // layer-1 output
__device__ int    g_cnt [N_NODES];            // per-dst degree / insertion cursor
__device__ float  g_dinvf[N_NODES];           // rsqrt(deg+1)
__device__ int    g_psrc[N_NODES * SLOTS];    // padded bucket: src ids

// Pre-split weights, transposed to n-major: Wt[n][k], bf16 hi/lo
__device__ __nv_bfloat16 g_wt_hi[2][DIM * DIM];
__device__ __nv_bfloat16 g_wt_lo[2][DIM * DIM];

// ---------------------------------------------------------------------------
// Precompute
// ---------------------------------------------------------------------------
__global__ void zero_cnt_kernel() {
    int i = blockIdx.x * blockDim.x + threadIdx.x;
    if (i < N_NODES) g_cnt[i] = 0;
}

__global__ void bucket_kernel(const int* __restrict__ src, const int* __restrict__ dst) {
    int base = (blockIdx.x * blockDim.x + threadIdx.x) * 4;
    if (base < E_EDGES) {   // E divisible by 4
        int4 d4 = *(const int4*)(dst + base);
        int4 s4 = *(const int4*)(src + base);
        int p0 = atomicAdd(&g_cnt[d4.x], 1);
        int p1 = atomicAdd(&g_cnt[d4.y], 1);
        int p2 = atomicAdd(&g_cnt[d4.z], 1);
        int p3 = atomicAdd(&g_cnt[d4.w], 1);
        g_psrc[d4.x * SLOTS + p0] = s4.x;
        g_psrc[d4.y * SLOTS + p1] = s4.y;
        g_psrc[d4.z * SLOTS + p2] = s4.z;
        g_psrc[d4.w * SLOTS + p3] = s4.w;
    }
}

__global__ void dinv_kernel() {
    int i = blockIdx.x * blockDim.x + threadIdx.x;
    if (i < N_NODES) g_dinvf[i] = rsqrtf((float)(g_cnt[i] + 1));
}

// ---------------------------------------------------------------------------
// Weight prep: split BOTH W (k-major [k][n]) into bf16 hi/lo, transposed [n][k]
// ---------------------------------------------------------------------------
__global__ void wsplit_kernel(const float* __restrict__ W0, const float* __restrict__ W1) {
    int t = blockIdx.x * blockDim.x + threadIdx.x;   // 2 * 16384
    if (t < 2 * DIM * DIM) {
        int which = t >> 14;
        int idx   = t & (DIM * DIM - 1);
        int k = idx >> 7, n = idx & 127;
        float v = (which ? W1 : W0)[idx];
        __nv_bfloat16 h = __float2bfloat16(v);
        __nv_bfloat16 l = __float2bfloat16(v - __bfloat162float(h));
        g_wt_hi[which][n * DIM + k] = h;
        g_wt_lo[which][n * DIM + k] = l;
    }
}

// ---------------------------------------------------------------------------
// Tensor-core GEMM: C[n,128] = A[n,128] @ W[128,128] in split-bf16
// Dual epilogue: fp32 C + fp16 Cf (gather copy).
// ---------------------------------------------------------------------------
#define GBM  128
#define GBK  32
#define GPAD 40

__device__ __forceinline__ void mma16816(float* c, const unsigned* a, const unsigned* b) {
    asm volatile(
        "mma.sync.aligned.m16n8k16.row.col.f32.bf16.bf16.f32 "
        "{%0,%1,%2,%3}, {%4,%5,%6,%7}, {%8,%9}, {%0,%1,%2,%3};"
        : "+f"(c[0]), "+f"(c[1]), "+f"(c[2]), "+f"(c[3])
        : "r"(a[0]), "r"(a[1]), "r"(a[2]), "r"(a[3]), "r"(b[0]), "r"(b[1]));
}

__global__ __launch_bounds__(256) void gemm_tc_kernel(
    const float* __restrict__ A,
    const __nv_bfloat16* __restrict__ Wt_hi,
    const __nv_bfloat16* __restrict__ Wt_lo,
    float* __restrict__ C, __half* __restrict__ Cf, int n)
{
    __shared__ __nv_bfloat16 sAh[GBM][GPAD];
    __shared__ __nv_bfloat16 sAl[GBM][GPAD];
    __shared__ __nv_bfloat16 sWh[DIM][GPAD];
    __shared__ __nv_bfloat16 sWl[DIM][GPAD];

    const int tid   = threadIdx.x;
    const int lane  = tid & 31;
    const int w     = tid >> 5;
    const int wm    = w & 3;
    const int wn    = w >> 2;
    const int gq    = lane >> 2;
    const int gp    = lane & 3;
    const int row0  = blockIdx.x * GBM;

    float c[2][8][4];
    #pragma unroll
    for (int im = 0; im < 2; im++)
        #pragma unroll
        for (int j = 0; j < 8; j++)
            #pragma unroll
            for (int q = 0; q < 4; q++) c[im][j][q] = 0.f;

    for (int kc = 0; kc < DIM; kc += GBK) {
        #pragma unroll
        for (int i = 0; i < 8; i++) {
            int idx = tid + i * 256;
            int m   = idx >> 4;
            int k2  = (idx & 15) * 2;
            int row = row0 + m;
            float2 v = (row < n) ? *(const float2*)(A + (size_t)row * DIM + kc + k2)
                                 : make_float2(0.f, 0.f);
            __nv_bfloat16 hx = __float2bfloat16(v.x);
            __nv_bfloat16 hy = __float2bfloat16(v.y);
            __nv_bfloat16 lx = __float2bfloat16(v.x - __bfloat162float(hx));
            __nv_bfloat16 ly = __float2bfloat16(v.y - __bfloat162float(hy));
            __nv_bfloat162 ph; ph.x = hx; ph.y = hy;
            __nv_bfloat162 pl; pl.x = lx; pl.y = ly;
            *(__nv_bfloat162*)&sAh[m][k2] = ph;
            *(__nv_bfloat162*)&sAl[m][k2] = pl;
        }
        #pragma unroll
        for (int i = 0; i < 8; i++) {
            int idx = tid + i * 256;
            int nn  = idx >> 4;
            int kp  = (idx & 15) * 2;
            *(unsigned*)&sWh[nn][kp] = *(const unsigned*)(Wt_hi + nn * DIM + kc + kp);
            *(unsigned*)&sWl[nn][kp] = *(const unsigned*)(Wt_lo + nn * DIM + kc + kp);
        }
        __syncthreads();

        #pragma unroll
        for (int ks = 0; ks < 2; ks++) {
            const int kb = ks * 16;
            unsigned bh[8][2], bl[8][2];
            #pragma unroll
            for (int j = 0; j < 8; j++) {
                int nn = wn * 64 + j * 8 + gq;
                bh[j][0] = *(const unsigned*)&sWh[nn][kb + gp * 2];
                bh[j][1] = *(const unsigned*)&sWh[nn][kb + gp * 2 + 8];
                bl[j][0] = *(const unsigned*)&sWl[nn][kb + gp * 2];
                bl[j][1] = *(const unsigned*)&sWl[nn][kb + gp * 2 + 8];
            }
            #pragma unroll
            for (int im = 0; im < 2; im++) {
                int mr = wm * 32 + im * 16 + gq;
                unsigned ah[4], al[4];
                ah[0] = *(const unsigned*)&sAh[mr    ][kb + gp * 2];
                ah[1] = *(const unsigned*)&sAh[mr + 8][kb + gp * 2];
                ah[2] = *(const unsigned*)&sAh[mr    ][kb + gp * 2 + 8];
                ah[3] = *(const unsigned*)&sAh[mr + 8][kb + gp * 2 + 8];
                al[0] = *(const unsigned*)&sAl[mr    ][kb + gp * 2];
                al[1] = *(const unsigned*)&sAl[mr + 8][kb + gp * 2];
                al[2] = *(const unsigned*)&sAl[mr    ][kb + gp * 2 + 8];
                al[3] = *(const unsigned*)&sAl[mr + 8][kb + gp * 2 + 8];
                #pragma unroll
                for (int j = 0; j < 8; j++) {
                    mma16816(c[im][j], ah, bh[j]);
                    mma16816(c[im][j], ah, bl[j]);
                    mma16816(c[im][j], al, bh[j]);
                }
            }
        }
        __syncthreads();
    }

    #pragma unroll
    for (int im = 0; im < 2; im++) {
        int mr = row0 + wm * 32 + im * 16 + gq;
        #pragma unroll
        for (int j = 0; j < 8; j++) {
            int col = wn * 64 + j * 8 + gp * 2;
            if (mr < n) {
                *(float2*)(C + (size_t)mr * DIM + col) = make_float2(c[im][j][0], c[im][j][1]);
                *(__half2*)(Cf + (size_t)mr * DIM + col) = __floats2half2_rn(c[im][j][0], c[im][j][1]);
            }
            if (mr + 8 < n) {
                *(float2*)(C + (size_t)(mr + 8) * DIM + col) = make_float2(c[im][j][2], c[im][j][3]);
                *(__half2*)(Cf + (size_t)(mr + 8) * DIM + col) = __floats2half2_rn(c[im][j][2], c[im][j][3]);
            }
        }
    }
}

// ---------------------------------------------------------------------------
// Fused aggregate: warp per node, fp16 gathers.
// Edge indices + src dinv preloaded COALESCED (3 slots/lane), distributed via
// shfl -> exactly 1 LDG per edge in the hot loop.
// out[d] = relu( h[d]*dv^2 + dv * sum_e hf[src_e]*dinv[src_e] + b )
// ---------------------------------------------------------------------------
__global__ __launch_bounds__(256) void aggregate_kernel(
    const float* __restrict__ h, const __half* __restrict__ hf,
    const float* __restrict__ b, float* __restrict__ out,
    int node_base, int node_count)
{
    const int lane = threadIdx.x & 31;
    const int nrel = (blockIdx.x * blockDim.x + threadIdx.x) >> 5;
    if (nrel >= node_count) return;
    const int node = node_base + nrel;

    const int deg  = g_cnt[node];
    const float dv = g_dinvf[node];
    const int* sp  = g_psrc + node * SLOTS;

    // Preload this node's edge list + src dinv, coalesced (3 x 32 slots)
    int   idxA[3];
    float dvA [3];
    #pragma unroll
    for (int j = 0; j < 3; j++) {
        int slot = lane + j * 32;
        bool v = slot < deg;
        int s = v ? sp[slot] : 0;
        idxA[j] = s;
        dvA[j]  = v ? g_dinvf[s] : 0.f;
    }

    float4 es = make_float4(0.f, 0.f, 0.f, 0.f);

    #pragma unroll
    for (int blk = 0; blk < 3; blk++) {
        int lim = deg - blk * 32;
        if (lim <= 0) break;
        if (lim > 32) lim = 32;
        const int idxc = idxA[blk];
        const float dvc = dvA[blk];

        int i = 0;
        for (; i + 8 <= lim; i += 8) {
            uint2 raw[8];
            float nm[8];
            #pragma unroll
            for (int u = 0; u < 8; u++) {
                int   s = __shfl_sync(0xffffffffu, idxc, i + u);
                nm[u]   = __shfl_sync(0xffffffffu, dvc,  i + u);
                raw[u]  = *(const uint2*)(hf + (size_t)s * DIM + lane * 4);
            }
            #pragma unroll
            for (int u = 0; u < 8; u++) {
                float2 f0 = __half22float2(*(__half2*)&raw[u].x);
                float2 f1 = __half22float2(*(__half2*)&raw[u].y);
                es.x += f0.x * nm[u]; es.y += f0.y * nm[u];
                es.z += f1.x * nm[u]; es.w += f1.y * nm[u];
            }
        }
        for (; i < lim; i++) {
            int   s  = __shfl_sync(0xffffffffu, idxc, i);
            float nm = __shfl_sync(0xffffffffu, dvc,  i);
            uint2 raw = *(const uint2*)(hf + (size_t)s * DIM + lane * 4);
            float2 f0 = __half22float2(*(__half2*)&raw.x);
            float2 f1 = __half22float2(*(__half2*)&raw.y);
            es.x += f0.x * nm; es.y += f0.y * nm;
            es.z += f1.x * nm; es.w += f1.y * nm;
        }
    }

    float4 acc = *(const float4*)(h + (size_t)node * DIM + lane * 4);
    const float sc = dv * dv;
    float4 b4 = *(const float4*)(b + lane * 4);
    acc.x = fmaxf(acc.x * sc + es.x * dv + b4.x, 0.f);
    acc.y = fmaxf(acc.y * sc + es.y * dv + b4.y, 0.f);
    acc.z = fmaxf(acc.z * sc + es.z * dv + b4.z, 0.f);
    acc.w = fmaxf(acc.w * sc + es.w * dv + b4.w, 0.f);
    *(float4*)(out + (size_t)node * DIM + lane * 4) = acc;
}

// ---------------------------------------------------------------------------
// Launch: two-stream fork-join, 4-chunk agg1/gemm2 pipeline (race-free via
// separate layer-2 buffers g_h2/g_hf2)
// ---------------------------------------------------------------------------
extern "C" void kernel_launch(void* const* d_in, const int* in_sizes, int n_in,
                              void* d_out, int out_size)
{
    const float* x   = (const float*)d_in[0];
    const int*   ei  = (const int*)  d_in[1];
    const float* W0  = (const float*)d_in[2];
    const float* b0  = (const float*)d_in[3];
    const float* W1  = (const float*)d_in[4];
    const float* b1  = (const float*)d_in[5];
    float*       out = (float*)d_out;

    const int* src = ei;
    const int* dst = ei + E_EDGES;

    float *h_ptr, *h2_ptr, *x1_ptr;
    __half *hf_ptr, *hf2_ptr;
    __nv_bfloat16 *whi_ptr, *wlo_ptr;
    cudaGetSymbolAddress((void**)&h_ptr,   g_h);
    cudaGetSymbolAddress((void**)&hf_ptr,  g_hf);
    cudaGetSymbolAddress((void**)&h2_ptr,  g_h2);
    cudaGetSymbolAddress((void**)&hf2_ptr, g_hf2);
    cudaGetSymbolAddress((void**)&x1_ptr,  g_x1);
    cudaGetSymbolAddress((void**)&whi_ptr, g_wt_hi);
    cudaGetSymbolAddress((void**)&wlo_ptr, g_wt_lo);

    const int TB = 256;
    const int gridN   = (N_NODES + TB - 1) / TB;
    const int gridE4  = (E_EDGES / 4 + TB - 1) / TB;
    const int gridG   = (N_NODES + GBM - 1) / GBM;
    const int gridGc  = (CHUNK + GBM - 1) / GBM;
    const int gridA   = (N_NODES * 32 + TB - 1) / TB;
    const int gridAc  = (CHUNK * 32 + TB - 1) / TB;
    const int gridW   = (2 * DIM * DIM + TB - 1) / TB;

    cudaStream_t s2;
    cudaStreamCreate(&s2);
    cudaEvent_t evF, evP, evG1, evB;
    cudaEventCreateWithFlags(&evF,  cudaEventDisableTiming);
    cudaEventCreateWithFlags(&evP,  cudaEventDisableTiming);
    cudaEventCreateWithFlags(&evG1, cudaEventDisableTiming);
    cudaEventCreateWithFlags(&evB,  cudaEventDisableTiming);

    cudaEventRecord(evF, 0);
    cudaStreamWaitEvent(s2, evF, 0);

    // Stream 0: graph precompute
    zero_cnt_kernel<<<gridN, TB>>>();
    bucket_kernel<<<gridE4, TB>>>(src, dst);
    dinv_kernel<<<gridN, TB>>>();
    cudaEventRecord(evP, 0);

    // Stream s2: weight split + full layer-1 GEMM -> g_h/g_hf
    wsplit_kernel<<<gridW, TB, 0, s2>>>(W0, W1);
    gemm_tc_kernel<<<gridG, TB, 0, s2>>>(x, whi_ptr, wlo_ptr, h_ptr, hf_ptr, N_NODES);
    cudaEventRecord(evG1, s2);

    const __nv_bfloat16* w1h = whi_ptr + DIM * DIM;
    const __nv_bfloat16* w1l = wlo_ptr + DIM * DIM;

    // Chunk pipeline: agg1 reads g_hf (layer-1, read-only from here on);
    // gemm2 writes g_h2/g_hf2 (disjoint) -> no cross-chunk race.
    cudaStreamWaitEvent(0, evG1, 0);    // s0 needs gemm1 (has precompute in-order)
    cudaStreamWaitEvent(s2, evP, 0);    // s2 needs precompute (has gemm1 in-order)

    for (int c = 0; c < 4; c++) {
        cudaStream_t st = (c & 1) ? s2 : (cudaStream_t)0;
        int base = c * CHUNK;
        aggregate_kernel<<<gridAc, TB, 0, st>>>(h_ptr, hf_ptr, b0, x1_ptr, base, CHUNK);
        gemm_tc_kernel<<<gridGc, TB, 0, st>>>(
            x1_ptr + (size_t)base * DIM, w1h, w1l,
            h2_ptr + (size_t)base * DIM, hf2_ptr + (size_t)base * DIM, CHUNK);
    }

    cudaEventRecord(evB, s2);
    cudaStreamWaitEvent(0, evB, 0);

    // Final aggregate over layer-2 buffers
    aggregate_kernel<<<gridA, TB>>>(h2_ptr, hf2_ptr, b1, out, 0, N_NODES);
}

// round 13
// speedup vs baseline: 1.0738x; 1.0738x over previous
#include <cuda_runtime.h>
#include <cuda_bf16.h>
#include <cuda_fp16.h>

#define N_NODES 50000
#define NODE_HALF 25000
#define E_EDGES 1600000
#define DIM     128
#define SLOTS   96      // max degree bucket capacity (Poisson(32): P(>96) ~ 1e-20)

// ---------------------------------------------------------------------------
// Scratch (device globals — no allocation allowed)
// Layer-1 GEMM writes g_h/g_hf; layer-2 GEMM writes g_h2/g_hf2 so agg1's
// random gathers from g_hf never race with gemm2's writes.
// ---------------------------------------------------------------------------
__device__ float  g_h  [N_NODES * DIM];       // layer-1 h (fp32)
__device__ __half g_hf [N_NODES * DIM];       // layer-1 h (fp16 gather copy)
__device__ float  g_h2 [N_NODES * DIM];       // layer-2 h (fp32)
__device__ __half g_hf2[N_NODES * DIM];       // layer-2 h (fp16 gather copy)
__device__ float  g_x1 [N_NODES * DIM];       // layer-1 output
__device__ int    g_cnt [N_NODES];            // per-dst degree / insertion cursor
__device__ float  g_dinvf[N_NODES];           // rsqrt(deg+1)
__device__ int2   g_pedge[N_NODES * SLOTS];   // padded: {src, __float_as_int(norm)}

// Pre-split weights, transposed to n-major: Wt[n][k], bf16 hi/lo
__device__ __nv_bfloat16 g_wt_hi[2][DIM * DIM];
__device__ __nv_bfloat16 g_wt_lo[2][DIM * DIM];

// ---------------------------------------------------------------------------
// Precompute
// ---------------------------------------------------------------------------
__global__ void zero_cnt_kernel() {
    int i = blockIdx.x * blockDim.x + threadIdx.x;
    if (i < N_NODES) g_cnt[i] = 0;
}

__global__ void bucket_kernel(const int* __restrict__ src, const int* __restrict__ dst) {
    int base = (blockIdx.x * blockDim.x + threadIdx.x) * 4;
    if (base < E_EDGES) {   // E divisible by 4
        int4 d4 = *(const int4*)(dst + base);
        int4 s4 = *(const int4*)(src + base);
        int p0 = atomicAdd(&g_cnt[d4.x], 1);
        int p1 = atomicAdd(&g_cnt[d4.y], 1);
        int p2 = atomicAdd(&g_cnt[d4.z], 1);
        int p3 = atomicAdd(&g_cnt[d4.w], 1);
        g_pedge[d4.x * SLOTS + p0].x = s4.x;
        g_pedge[d4.y * SLOTS + p1].x = s4.y;
        g_pedge[d4.z * SLOTS + p2].x = s4.z;
        g_pedge[d4.w * SLOTS + p3].x = s4.w;
    }
}

__global__ void dinv_kernel() {
    int i = blockIdx.x * blockDim.x + threadIdx.x;
    if (i < N_NODES) g_dinvf[i] = rsqrtf((float)(g_cnt[i] + 1));
}

// Fill premultiplied norms: warp per node, coalesced over slots.
__global__ __launch_bounds__(256) void normfill_kernel() {
    const int lane = threadIdx.x & 31;
    const int node = (blockIdx.x * blockDim.x + threadIdx.x) >> 5;
    if (node >= N_NODES) return;
    const int deg  = g_cnt[node];
    const float dv = g_dinvf[node];
    int2* ep = g_pedge + node * SLOTS;
    #pragma unroll
    for (int j = 0; j < 3; j++) {
        int slot = lane + j * 32;
        if (slot < deg) {
            int s = ep[slot].x;
            ep[slot].y = __float_as_int(dv * g_dinvf[s]);
        }
    }
}

// ---------------------------------------------------------------------------
// Weight prep: split BOTH W (k-major [k][n]) into bf16 hi/lo, transposed [n][k]
// ---------------------------------------------------------------------------
__global__ void wsplit_kernel(const float* __restrict__ W0, const float* __restrict__ W1) {
    int t = blockIdx.x * blockDim.x + threadIdx.x;   // 2 * 16384
    if (t < 2 * DIM * DIM) {
        int which = t >> 14;
        int idx   = t & (DIM * DIM - 1);
        int k = idx >> 7, n = idx & 127;
        float v = (which ? W1 : W0)[idx];
        __nv_bfloat16 h = __float2bfloat16(v);
        __nv_bfloat16 l = __float2bfloat16(v - __bfloat162float(h));
        g_wt_hi[which][n * DIM + k] = h;
        g_wt_lo[which][n * DIM + k] = l;
    }
}

// ---------------------------------------------------------------------------
// Tensor-core GEMM: C[n,128] = A[n,128] @ W[128,128] in split-bf16
// Dual epilogue: fp32 C + fp16 Cf (gather copy).
// ---------------------------------------------------------------------------
#define GBM  128
#define GBK  32
#define GPAD 40

__device__ __forceinline__ void mma16816(float* c, const unsigned* a, const unsigned* b) {
    asm volatile(
        "mma.sync.aligned.m16n8k16.row.col.f32.bf16.bf16.f32 "
        "{%0,%1,%2,%3}, {%4,%5,%6,%7}, {%8,%9}, {%0,%1,%2,%3};"
        : "+f"(c[0]), "+f"(c[1]), "+f"(c[2]), "+f"(c[3])
        : "r"(a[0]), "r"(a[1]), "r"(a[2]), "r"(a[3]), "r"(b[0]), "r"(b[1]));
}

__global__ __launch_bounds__(256) void gemm_tc_kernel(
    const float* __restrict__ A,
    const __nv_bfloat16* __restrict__ Wt_hi,
    const __nv_bfloat16* __restrict__ Wt_lo,
    float* __restrict__ C, __half* __restrict__ Cf, int n)
{
    __shared__ __nv_bfloat16 sAh[GBM][GPAD];
    __shared__ __nv_bfloat16 sAl[GBM][GPAD];
    __shared__ __nv_bfloat16 sWh[DIM][GPAD];
    __shared__ __nv_bfloat16 sWl[DIM][GPAD];

    const int tid   = threadIdx.x;
    const int lane  = tid & 31;
    const int w     = tid >> 5;
    const int wm    = w & 3;
    const int wn    = w >> 2;
    const int gq    = lane >> 2;
    const int gp    = lane & 3;
    const int row0  = blockIdx.x * GBM;

    float c[2][8][4];
    #pragma unroll
    for (int im = 0; im < 2; im++)
        #pragma unroll
        for (int j = 0; j < 8; j++)
            #pragma unroll
            for (int q = 0; q < 4; q++) c[im][j][q] = 0.f;

    for (int kc = 0; kc < DIM; kc += GBK) {
        #pragma unroll
        for (int i = 0; i < 8; i++) {
            int idx = tid + i * 256;
            int m   = idx >> 4;
            int k2  = (idx & 15) * 2;
            int row = row0 + m;
            float2 v = (row < n) ? *(const float2*)(A + (size_t)row * DIM + kc + k2)
                                 : make_float2(0.f, 0.f);
            __nv_bfloat16 hx = __float2bfloat16(v.x);
            __nv_bfloat16 hy = __float2bfloat16(v.y);
            __nv_bfloat16 lx = __float2bfloat16(v.x - __bfloat162float(hx));
            __nv_bfloat16 ly = __float2bfloat16(v.y - __bfloat162float(hy));
            __nv_bfloat162 ph; ph.x = hx; ph.y = hy;
            __nv_bfloat162 pl; pl.x = lx; pl.y = ly;
            *(__nv_bfloat162*)&sAh[m][k2] = ph;
            *(__nv_bfloat162*)&sAl[m][k2] = pl;
        }
        #pragma unroll
        for (int i = 0; i < 8; i++) {
            int idx = tid + i * 256;
            int nn  = idx >> 4;
            int kp  = (idx & 15) * 2;
            *(unsigned*)&sWh[nn][kp] = *(const unsigned*)(Wt_hi + nn * DIM + kc + kp);
            *(unsigned*)&sWl[nn][kp] = *(const unsigned*)(Wt_lo + nn * DIM + kc + kp);
        }
        __syncthreads();

        #pragma unroll
        for (int ks = 0; ks < 2; ks++) {
            const int kb = ks * 16;
            unsigned bh[8][2], bl[8][2];
            #pragma unroll
            for (int j = 0; j < 8; j++) {
                int nn = wn * 64 + j * 8 + gq;
                bh[j][0] = *(const unsigned*)&sWh[nn][kb + gp * 2];
                bh[j][1] = *(const unsigned*)&sWh[nn][kb + gp * 2 + 8];
                bl[j][0] = *(const unsigned*)&sWl[nn][kb + gp * 2];
                bl[j][1] = *(const unsigned*)&sWl[nn][kb + gp * 2 + 8];
            }
            #pragma unroll
            for (int im = 0; im < 2; im++) {
                int mr = wm * 32 + im * 16 + gq;
                unsigned ah[4], al[4];
                ah[0] = *(const unsigned*)&sAh[mr    ][kb + gp * 2];
                ah[1] = *(const unsigned*)&sAh[mr + 8][kb + gp * 2];
                ah[2] = *(const unsigned*)&sAh[mr    ][kb + gp * 2 + 8];
                ah[3] = *(const unsigned*)&sAh[mr + 8][kb + gp * 2 + 8];
                al[0] = *(const unsigned*)&sAl[mr    ][kb + gp * 2];
                al[1] = *(const unsigned*)&sAl[mr + 8][kb + gp * 2];
                al[2] = *(const unsigned*)&sAl[mr    ][kb + gp * 2 + 8];
                al[3] = *(const unsigned*)&sAl[mr + 8][kb + gp * 2 + 8];
                #pragma unroll
                for (int j = 0; j < 8; j++) {
                    mma16816(c[im][j], ah, bh[j]);
                    mma16816(c[im][j], ah, bl[j]);
                    mma16816(c[im][j], al, bh[j]);
                }
            }
        }
        __syncthreads();
    }

    #pragma unroll
    for (int im = 0; im < 2; im++) {
        int mr = row0 + wm * 32 + im * 16 + gq;
        #pragma unroll
        for (int j = 0; j < 8; j++) {
            int col = wn * 64 + j * 8 + gp * 2;
            if (mr < n) {
                *(float2*)(C + (size_t)mr * DIM + col) = make_float2(c[im][j][0], c[im][j][1]);
                *(__half2*)(Cf + (size_t)mr * DIM + col) = __floats2half2_rn(c[im][j][0], c[im][j][1]);
            }
            if (mr + 8 < n) {
                *(float2*)(C + (size_t)(mr + 8) * DIM + col) = make_float2(c[im][j][2], c[im][j][3]);
                *(__half2*)(Cf + (size_t)(mr + 8) * DIM + col) = __floats2half2_rn(c[im][j][2], c[im][j][3]);
            }
        }
    }
}

// ---------------------------------------------------------------------------
// Fused aggregate: warp per node, fp16 gathers, premultiplied norms.
// Per edge: 1 broadcast int2 load + 1 row gather (2 LDG issues).
// out[d] = relu( h[d]*dv^2 + sum_e hf[src_e]*norm_e + b )
// ---------------------------------------------------------------------------
__global__ __launch_bounds__(256) void aggregate_kernel(
    const float* __restrict__ h, const __half* __restrict__ hf,
    const float* __restrict__ b, float* __restrict__ out,
    int node_base, int node_count)
{
    const int lane = threadIdx.x & 31;
    const int nrel = (blockIdx.x * blockDim.x + threadIdx.x) >> 5;
    if (nrel >= node_count) return;
    const int node = node_base + nrel;

    const int deg  = g_cnt[node];
    const float dv = g_dinvf[node];
    const int2* ep = g_pedge + node * SLOTS;

    float4 acc = *(const float4*)(h + (size_t)node * DIM + lane * 4);
    const float sc = dv * dv;
    acc.x *= sc; acc.y *= sc; acc.z *= sc; acc.w *= sc;

    int e = 0;
    for (; e + 8 <= deg; e += 8) {
        int2 ed[8];
        #pragma unroll
        for (int i = 0; i < 8; i++) ed[i] = ep[e + i];
        uint2 raw[8];
        #pragma unroll
        for (int i = 0; i < 8; i++)
            raw[i] = *(const uint2*)(hf + (size_t)ed[i].x * DIM + lane * 4);
        #pragma unroll
        for (int i = 0; i < 8; i++) {
            float nm = __int_as_float(ed[i].y);
            float2 f0 = __half22float2(*(__half2*)&raw[i].x);
            float2 f1 = __half22float2(*(__half2*)&raw[i].y);
            acc.x += f0.x * nm; acc.y += f0.y * nm;
            acc.z += f1.x * nm; acc.w += f1.y * nm;
        }
    }
    for (; e < deg; e++) {
        int2 e0 = ep[e];
        float nm = __int_as_float(e0.y);
        uint2 raw = *(const uint2*)(hf + (size_t)e0.x * DIM + lane * 4);
        float2 f0 = __half22float2(*(__half2*)&raw.x);
        float2 f1 = __half22float2(*(__half2*)&raw.y);
        acc.x += f0.x * nm; acc.y += f0.y * nm;
        acc.z += f1.x * nm; acc.w += f1.y * nm;
    }

    float4 b4 = *(const float4*)(b + lane * 4);
    acc.x = fmaxf(acc.x + b4.x, 0.f);
    acc.y = fmaxf(acc.y + b4.y, 0.f);
    acc.z = fmaxf(acc.z + b4.z, 0.f);
    acc.w = fmaxf(acc.w + b4.w, 0.f);
    *(float4*)(out + (size_t)node * DIM + lane * 4) = acc;
}

// ---------------------------------------------------------------------------
// Launch: two-stream fork-join, 2-chunk agg1/gemm2 pipeline (race-free via
// separate layer-2 buffers g_h2/g_hf2)
// ---------------------------------------------------------------------------
extern "C" void kernel_launch(void* const* d_in, const int* in_sizes, int n_in,
                              void* d_out, int out_size)
{
    const float* x   = (const float*)d_in[0];
    const int*   ei  = (const int*)  d_in[1];
    const float* W0  = (const float*)d_in[2];
    const float* b0  = (const float*)d_in[3];
    const float* W1  = (const float*)d_in[4];
    const float* b1  = (const float*)d_in[5];
    float*       out = (float*)d_out;

    const int* src = ei;
    const int* dst = ei + E_EDGES;

    float *h_ptr, *h2_ptr, *x1_ptr;
    __half *hf_ptr, *hf2_ptr;
    __nv_bfloat16 *whi_ptr, *wlo_ptr;
    cudaGetSymbolAddress((void**)&h_ptr,   g_h);
    cudaGetSymbolAddress((void**)&hf_ptr,  g_hf);
    cudaGetSymbolAddress((void**)&h2_ptr,  g_h2);
    cudaGetSymbolAddress((void**)&hf2_ptr, g_hf2);
    cudaGetSymbolAddress((void**)&x1_ptr,  g_x1);
    cudaGetSymbolAddress((void**)&whi_ptr, g_wt_hi);
    cudaGetSymbolAddress((void**)&wlo_ptr, g_wt_lo);

    const int TB = 256;
    const int gridN   = (N_NODES + TB - 1) / TB;
    const int gridE4  = (E_EDGES / 4 + TB - 1) / TB;
    const int gridG   = (N_NODES + GBM - 1) / GBM;
    const int gridGh  = (NODE_HALF + GBM - 1) / GBM;
    const int gridA   = (N_NODES * 32 + TB - 1) / TB;
    const int gridAh  = (NODE_HALF * 32 + TB - 1) / TB;
    const int gridW   = (2 * DIM * DIM + TB - 1) / TB;

    cudaStream_t s2;
    cudaStreamCreate(&s2);
    cudaEvent_t evF, evP, evG1, evB;
    cudaEventCreateWithFlags(&evF,  cudaEventDisableTiming);
    cudaEventCreateWithFlags(&evP,  cudaEventDisableTiming);
    cudaEventCreateWithFlags(&evG1, cudaEventDisableTiming);
    cudaEventCreateWithFlags(&evB,  cudaEventDisableTiming);

    cudaEventRecord(evF, 0);
    cudaStreamWaitEvent(s2, evF, 0);

    // Stream 0: graph precompute (normfill overlaps gemm1 on s2)
    zero_cnt_kernel<<<gridN, TB>>>();
    bucket_kernel<<<gridE4, TB>>>(src, dst);
    dinv_kernel<<<gridN, TB>>>();
    normfill_kernel<<<gridA, TB>>>();
    cudaEventRecord(evP, 0);

    // Stream s2: weight split + full layer-1 GEMM -> g_h/g_hf
    wsplit_kernel<<<gridW, TB, 0, s2>>>(W0, W1);
    gemm_tc_kernel<<<gridG, TB, 0, s2>>>(x, whi_ptr, wlo_ptr, h_ptr, hf_ptr, N_NODES);
    cudaEventRecord(evG1, s2);

    const __nv_bfloat16* w1h = whi_ptr + DIM * DIM;
    const __nv_bfloat16* w1l = wlo_ptr + DIM * DIM;

    // 2-chunk pipeline: agg1 reads g_hf (read-only now); gemm2 writes
    // g_h2/g_hf2 (disjoint) -> race-free.
    cudaStreamWaitEvent(0, evG1, 0);    // s0 needs gemm1 (precompute in-order)
    cudaStreamWaitEvent(s2, evP, 0);    // s2 needs precompute (gemm1 in-order)

    // chunk 0 on stream 0
    aggregate_kernel<<<gridAh, TB>>>(h_ptr, hf_ptr, b0, x1_ptr, 0, NODE_HALF);
    gemm_tc_kernel<<<gridGh, TB>>>(x1_ptr, w1h, w1l, h2_ptr, hf2_ptr, NODE_HALF);

    // chunk 1 on stream s2
    aggregate_kernel<<<gridAh, TB, 0, s2>>>(h_ptr, hf_ptr, b0, x1_ptr, NODE_HALF, NODE_HALF);
    gemm_tc_kernel<<<gridGh, TB, 0, s2>>>(
        x1_ptr + (size_t)NODE_HALF * DIM, w1h, w1l,
        h2_ptr + (size_t)NODE_HALF * DIM, hf2_ptr + (size_t)NODE_HALF * DIM, NODE_HALF);
    cudaEventRecord(evB, s2);
    cudaStreamWaitEvent(0, evB, 0);

    // Final aggregate over layer-2 buffers
    aggregate_kernel<<<gridA, TB>>>(h2_ptr, hf2_ptr, b1, out, 0, N_NODES);
}

// round 14
// speedup vs baseline: 1.1759x; 1.0951x over previous
#include <cuda_runtime.h>
#include <cuda_bf16.h>
#include <cuda_fp16.h>

#define N_NODES 50000
#define NODE_HALF 25000
#define E_EDGES 1600000
#define DIM     128
#define SLOTS   96      // max degree bucket capacity (Poisson(32): P(>96) ~ 1e-20)

// ---------------------------------------------------------------------------
// Scratch (device globals — no allocation allowed)
// Layer-1 GEMM writes g_h/g_hf (hf UNSCALED); layer-2 GEMM writes g_h2/g_hf2
// (hf2 PRE-SCALED by dinv[row]). Dual buffers keep the agg1/gemm2 chunk
// pipeline race-free.
// ---------------------------------------------------------------------------
__device__ float  g_h  [N_NODES * DIM];       // layer-1 h (fp32)
__device__ __half g_hf [N_NODES * DIM];       // layer-1 h (fp16, unscaled)
__device__ float  g_h2 [N_NODES * DIM];       // layer-2 h (fp32)
__device__ __half g_hf2[N_NODES * DIM];       // layer-2 h (fp16, pre-scaled by dinv)
__device__ float  g_x1 [N_NODES * DIM];       // layer-1 output
__device__ int    g_cnt [N_NODES];            // per-dst degree / insertion cursor
__device__ float  g_dinvf[N_NODES];           // rsqrt(deg+1)
__device__ int    g_psrc[N_NODES * SLOTS];    // padded bucket: src ids (bare int)

// Pre-split weights, transposed to n-major: Wt[n][k], bf16 hi/lo
__device__ __nv_bfloat16 g_wt_hi[2][DIM * DIM];
__device__ __nv_bfloat16 g_wt_lo[2][DIM * DIM];

// ---------------------------------------------------------------------------
// Precompute
// ---------------------------------------------------------------------------
__global__ void zero_cnt_kernel() {
    int i = blockIdx.x * blockDim.x + threadIdx.x;
    if (i < N_NODES) g_cnt[i] = 0;
}

__global__ void bucket_kernel(const int* __restrict__ src, const int* __restrict__ dst) {
    int base = (blockIdx.x * blockDim.x + threadIdx.x) * 4;
    if (base < E_EDGES) {   // E divisible by 4
        int4 d4 = *(const int4*)(dst + base);
        int4 s4 = *(const int4*)(src + base);
        int p0 = atomicAdd(&g_cnt[d4.x], 1);
        int p1 = atomicAdd(&g_cnt[d4.y], 1);
        int p2 = atomicAdd(&g_cnt[d4.z], 1);
        int p3 = atomicAdd(&g_cnt[d4.w], 1);
        g_psrc[d4.x * SLOTS + p0] = s4.x;
        g_psrc[d4.y * SLOTS + p1] = s4.y;
        g_psrc[d4.z * SLOTS + p2] = s4.z;
        g_psrc[d4.w * SLOTS + p3] = s4.w;
    }
}

__global__ void dinv_kernel() {
    int i = blockIdx.x * blockDim.x + threadIdx.x;
    if (i < N_NODES) g_dinvf[i] = rsqrtf((float)(g_cnt[i] + 1));
}

// ---------------------------------------------------------------------------
// Weight prep: split BOTH W (k-major [k][n]) into bf16 hi/lo, transposed [n][k]
// ---------------------------------------------------------------------------
__global__ void wsplit_kernel(const float* __restrict__ W0, const float* __restrict__ W1) {
    int t = blockIdx.x * blockDim.x + threadIdx.x;   // 2 * 16384
    if (t < 2 * DIM * DIM) {
        int which = t >> 14;
        int idx   = t & (DIM * DIM - 1);
        int k = idx >> 7, n = idx & 127;
        float v = (which ? W1 : W0)[idx];
        __nv_bfloat16 h = __float2bfloat16(v);
        __nv_bfloat16 l = __float2bfloat16(v - __bfloat162float(h));
        g_wt_hi[which][n * DIM + k] = h;
        g_wt_lo[which][n * DIM + k] = l;
    }
}

// ---------------------------------------------------------------------------
// Tensor-core GEMM: C[n,128] = A[n,128] @ W[128,128] in split-bf16
// Dual epilogue: fp32 C + fp16 Cf. If rowscale != nullptr, Cf is scaled by
// rowscale[row] (used by layer 2 so gathers need no per-edge norm).
// ---------------------------------------------------------------------------
#define GBM  128
#define GBK  32
#define GPAD 40

__device__ __forceinline__ void mma16816(float* c, const unsigned* a, const unsigned* b) {
    asm volatile(
        "mma.sync.aligned.m16n8k16.row.col.f32.bf16.bf16.f32 "
        "{%0,%1,%2,%3}, {%4,%5,%6,%7}, {%8,%9}, {%0,%1,%2,%3};"
        : "+f"(c[0]), "+f"(c[1]), "+f"(c[2]), "+f"(c[3])
        : "r"(a[0]), "r"(a[1]), "r"(a[2]), "r"(a[3]), "r"(b[0]), "r"(b[1]));
}

__global__ __launch_bounds__(256) void gemm_tc_kernel(
    const float* __restrict__ A,
    const __nv_bfloat16* __restrict__ Wt_hi,
    const __nv_bfloat16* __restrict__ Wt_lo,
    float* __restrict__ C, __half* __restrict__ Cf,
    const float* __restrict__ rowscale, int n)
{
    __shared__ __nv_bfloat16 sAh[GBM][GPAD];
    __shared__ __nv_bfloat16 sAl[GBM][GPAD];
    __shared__ __nv_bfloat16 sWh[DIM][GPAD];
    __shared__ __nv_bfloat16 sWl[DIM][GPAD];

    const int tid   = threadIdx.x;
    const int lane  = tid & 31;
    const int w     = tid >> 5;
    const int wm    = w & 3;
    const int wn    = w >> 2;
    const int gq    = lane >> 2;
    const int gp    = lane & 3;
    const int row0  = blockIdx.x * GBM;

    float c[2][8][4];
    #pragma unroll
    for (int im = 0; im < 2; im++)
        #pragma unroll
        for (int j = 0; j < 8; j++)
            #pragma unroll
            for (int q = 0; q < 4; q++) c[im][j][q] = 0.f;

    for (int kc = 0; kc < DIM; kc += GBK) {
        #pragma unroll
        for (int i = 0; i < 8; i++) {
            int idx = tid + i * 256;
            int m   = idx >> 4;
            int k2  = (idx & 15) * 2;
            int row = row0 + m;
            float2 v = (row < n) ? *(const float2*)(A + (size_t)row * DIM + kc + k2)
                                 : make_float2(0.f, 0.f);
            __nv_bfloat16 hx = __float2bfloat16(v.x);
            __nv_bfloat16 hy = __float2bfloat16(v.y);
            __nv_bfloat16 lx = __float2bfloat16(v.x - __bfloat162float(hx));
            __nv_bfloat16 ly = __float2bfloat16(v.y - __bfloat162float(hy));
            __nv_bfloat162 ph; ph.x = hx; ph.y = hy;
            __nv_bfloat162 pl; pl.x = lx; pl.y = ly;
            *(__nv_bfloat162*)&sAh[m][k2] = ph;
            *(__nv_bfloat162*)&sAl[m][k2] = pl;
        }
        #pragma unroll
        for (int i = 0; i < 8; i++) {
            int idx = tid + i * 256;
            int nn  = idx >> 4;
            int kp  = (idx & 15) * 2;
            *(unsigned*)&sWh[nn][kp] = *(const unsigned*)(Wt_hi + nn * DIM + kc + kp);
            *(unsigned*)&sWl[nn][kp] = *(const unsigned*)(Wt_lo + nn * DIM + kc + kp);
        }
        __syncthreads();

        #pragma unroll
        for (int ks = 0; ks < 2; ks++) {
            const int kb = ks * 16;
            unsigned bh[8][2], bl[8][2];
            #pragma unroll
            for (int j = 0; j < 8; j++) {
                int nn = wn * 64 + j * 8 + gq;
                bh[j][0] = *(const unsigned*)&sWh[nn][kb + gp * 2];
                bh[j][1] = *(const unsigned*)&sWh[nn][kb + gp * 2 + 8];
                bl[j][0] = *(const unsigned*)&sWl[nn][kb + gp * 2];
                bl[j][1] = *(const unsigned*)&sWl[nn][kb + gp * 2 + 8];
            }
            #pragma unroll
            for (int im = 0; im < 2; im++) {
                int mr = wm * 32 + im * 16 + gq;
                unsigned ah[4], al[4];
                ah[0] = *(const unsigned*)&sAh[mr    ][kb + gp * 2];
                ah[1] = *(const unsigned*)&sAh[mr + 8][kb + gp * 2];
                ah[2] = *(const unsigned*)&sAh[mr    ][kb + gp * 2 + 8];
                ah[3] = *(const unsigned*)&sAh[mr + 8][kb + gp * 2 + 8];
                al[0] = *(const unsigned*)&sAl[mr    ][kb + gp * 2];
                al[1] = *(const unsigned*)&sAl[mr + 8][kb + gp * 2];
                al[2] = *(const unsigned*)&sAl[mr    ][kb + gp * 2 + 8];
                al[3] = *(const unsigned*)&sAl[mr + 8][kb + gp * 2 + 8];
                #pragma unroll
                for (int j = 0; j < 8; j++) {
                    mma16816(c[im][j], ah, bh[j]);
                    mma16816(c[im][j], ah, bl[j]);
                    mma16816(c[im][j], al, bh[j]);
                }
            }
        }
        __syncthreads();
    }

    #pragma unroll
    for (int im = 0; im < 2; im++) {
        int mr = row0 + wm * 32 + im * 16 + gq;
        float s0 = 1.f, s1 = 1.f;
        if (rowscale) {
            if (mr < n)     s0 = rowscale[mr];
            if (mr + 8 < n) s1 = rowscale[mr + 8];
        }
        #pragma unroll
        for (int j = 0; j < 8; j++) {
            int col = wn * 64 + j * 8 + gp * 2;
            if (mr < n) {
                *(float2*)(C + (size_t)mr * DIM + col) = make_float2(c[im][j][0], c[im][j][1]);
                *(__half2*)(Cf + (size_t)mr * DIM + col) =
                    __floats2half2_rn(c[im][j][0] * s0, c[im][j][1] * s0);
            }
            if (mr + 8 < n) {
                *(float2*)(C + (size_t)(mr + 8) * DIM + col) = make_float2(c[im][j][2], c[im][j][3]);
                *(__half2*)(Cf + (size_t)(mr + 8) * DIM + col) =
                    __floats2half2_rn(c[im][j][2] * s1, c[im][j][3] * s1);
            }
        }
    }
}

// ---------------------------------------------------------------------------
// Fused aggregate: warp per node, fp16 gathers, int4 meta (4 srcs / LDG).
// GATHER_DINV=true  (layer 1): es += hf[s] * dinv[s]   (hf unscaled)
// GATHER_DINV=false (layer 2): es += hf[s]             (hf pre-scaled by dinv)
// out[d] = relu( h[d]*dv^2 + dv * es + b )
// ---------------------------------------------------------------------------
template <bool GATHER_DINV>
__global__ __launch_bounds__(256) void aggregate_kernel(
    const float* __restrict__ h, const __half* __restrict__ hf,
    const float* __restrict__ b, float* __restrict__ out,
    int node_base, int node_count)
{
    const int lane = threadIdx.x & 31;
    const int nrel = (blockIdx.x * blockDim.x + threadIdx.x) >> 5;
    if (nrel >= node_count) return;
    const int node = node_base + nrel;

    const int deg  = g_cnt[node];
    const float dv = g_dinvf[node];
    const int* sp  = g_psrc + node * SLOTS;

    float4 es = make_float4(0.f, 0.f, 0.f, 0.f);

    int e = 0;
    for (; e + 8 <= deg; e += 8) {
        int4 m0 = *(const int4*)(sp + e);       // 4 srcs in one broadcast LDG
        int4 m1 = *(const int4*)(sp + e + 4);
        int s[8] = {m0.x, m0.y, m0.z, m0.w, m1.x, m1.y, m1.z, m1.w};
        uint2 raw[8];
        float nm[8];
        #pragma unroll
        for (int i = 0; i < 8; i++) {
            raw[i] = *(const uint2*)(hf + (size_t)s[i] * DIM + lane * 4);
            nm[i]  = GATHER_DINV ? g_dinvf[s[i]] : 1.f;
        }
        #pragma unroll
        for (int i = 0; i < 8; i++) {
            float2 f0 = __half22float2(*(__half2*)&raw[i].x);
            float2 f1 = __half22float2(*(__half2*)&raw[i].y);
            if (GATHER_DINV) {
                es.x += f0.x * nm[i]; es.y += f0.y * nm[i];
                es.z += f1.x * nm[i]; es.w += f1.y * nm[i];
            } else {
                es.x += f0.x; es.y += f0.y;
                es.z += f1.x; es.w += f1.y;
            }
        }
    }
    for (; e < deg; e++) {
        int s = sp[e];
        uint2 raw = *(const uint2*)(hf + (size_t)s * DIM + lane * 4);
        float2 f0 = __half22float2(*(__half2*)&raw.x);
        float2 f1 = __half22float2(*(__half2*)&raw.y);
        float nm = GATHER_DINV ? g_dinvf[s] : 1.f;
        es.x += f0.x * nm; es.y += f0.y * nm;
        es.z += f1.x * nm; es.w += f1.y * nm;
    }

    float4 acc = *(const float4*)(h + (size_t)node * DIM + lane * 4);
    const float sc = dv * dv;
    float4 b4 = *(const float4*)(b + lane * 4);
    acc.x = fmaxf(acc.x * sc + es.x * dv + b4.x, 0.f);
    acc.y = fmaxf(acc.y * sc + es.y * dv + b4.y, 0.f);
    acc.z = fmaxf(acc.z * sc + es.z * dv + b4.z, 0.f);
    acc.w = fmaxf(acc.w * sc + es.w * dv + b4.w, 0.f);
    *(float4*)(out + (size_t)node * DIM + lane * 4) = acc;
}

// ---------------------------------------------------------------------------
// Launch: two-stream fork-join, 2-chunk agg1/gemm2 pipeline (race-free via
// separate layer-2 buffers g_h2/g_hf2)
// ---------------------------------------------------------------------------
extern "C" void kernel_launch(void* const* d_in, const int* in_sizes, int n_in,
                              void* d_out, int out_size)
{
    const float* x   = (const float*)d_in[0];
    const int*   ei  = (const int*)  d_in[1];
    const float* W0  = (const float*)d_in[2];
    const float* b0  = (const float*)d_in[3];
    const float* W1  = (const float*)d_in[4];
    const float* b1  = (const float*)d_in[5];
    float*       out = (float*)d_out;

    const int* src = ei;
    const int* dst = ei + E_EDGES;

    float *h_ptr, *h2_ptr, *x1_ptr, *dinv_ptr;
    __half *hf_ptr, *hf2_ptr;
    __nv_bfloat16 *whi_ptr, *wlo_ptr;
    cudaGetSymbolAddress((void**)&h_ptr,    g_h);
    cudaGetSymbolAddress((void**)&hf_ptr,   g_hf);
    cudaGetSymbolAddress((void**)&h2_ptr,   g_h2);
    cudaGetSymbolAddress((void**)&hf2_ptr,  g_hf2);
    cudaGetSymbolAddress((void**)&x1_ptr,   g_x1);
    cudaGetSymbolAddress((void**)&dinv_ptr, g_dinvf);
    cudaGetSymbolAddress((void**)&whi_ptr,  g_wt_hi);
    cudaGetSymbolAddress((void**)&wlo_ptr,  g_wt_lo);

    const int TB = 256;
    const int gridN   = (N_NODES + TB - 1) / TB;
    const int gridE4  = (E_EDGES / 4 + TB - 1) / TB;
    const int gridG   = (N_NODES + GBM - 1) / GBM;
    const int gridGh  = (NODE_HALF + GBM - 1) / GBM;
    const int gridA   = (N_NODES * 32 + TB - 1) / TB;
    const int gridAh  = (NODE_HALF * 32 + TB - 1) / TB;
    const int gridW   = (2 * DIM * DIM + TB - 1) / TB;

    cudaStream_t s2;
    cudaStreamCreate(&s2);
    cudaEvent_t evF, evP, evG1, evB;
    cudaEventCreateWithFlags(&evF,  cudaEventDisableTiming);
    cudaEventCreateWithFlags(&evP,  cudaEventDisableTiming);
    cudaEventCreateWithFlags(&evG1, cudaEventDisableTiming);
    cudaEventCreateWithFlags(&evB,  cudaEventDisableTiming);

    cudaEventRecord(evF, 0);
    cudaStreamWaitEvent(s2, evF, 0);

    // Stream 0: graph precompute (~26us, hidden under wsplit+gemm1)
    zero_cnt_kernel<<<gridN, TB>>>();
    bucket_kernel<<<gridE4, TB>>>(src, dst);
    dinv_kernel<<<gridN, TB>>>();
    cudaEventRecord(evP, 0);

    // Stream s2: weight split + full layer-1 GEMM -> g_h/g_hf (hf unscaled)
    wsplit_kernel<<<gridW, TB, 0, s2>>>(W0, W1);
    gemm_tc_kernel<<<gridG, TB, 0, s2>>>(x, whi_ptr, wlo_ptr, h_ptr, hf_ptr,
                                         nullptr, N_NODES);
    cudaEventRecord(evG1, s2);

    const __nv_bfloat16* w1h = whi_ptr + DIM * DIM;
    const __nv_bfloat16* w1l = wlo_ptr + DIM * DIM;

    // 2-chunk pipeline: agg1 reads g_hf (read-only from here); gemm2 writes
    // g_h2/g_hf2 (disjoint, hf2 pre-scaled by dinv) -> race-free.
    cudaStreamWaitEvent(0, evG1, 0);    // s0 needs gemm1 (precompute in-order)
    cudaStreamWaitEvent(s2, evP, 0);    // s2 needs precompute (gemm1 in-order)

    // chunk 0 on stream 0
    aggregate_kernel<true><<<gridAh, TB>>>(h_ptr, hf_ptr, b0, x1_ptr, 0, NODE_HALF);
    gemm_tc_kernel<<<gridGh, TB>>>(x1_ptr, w1h, w1l, h2_ptr, hf2_ptr,
                                   dinv_ptr, NODE_HALF);

    // chunk 1 on stream s2
    aggregate_kernel<true><<<gridAh, TB, 0, s2>>>(h_ptr, hf_ptr, b0, x1_ptr,
                                                  NODE_HALF, NODE_HALF);
    gemm_tc_kernel<<<gridGh, TB, 0, s2>>>(
        x1_ptr + (size_t)NODE_HALF * DIM, w1h, w1l,
        h2_ptr + (size_t)NODE_HALF * DIM, hf2_ptr + (size_t)NODE_HALF * DIM,
        dinv_ptr + NODE_HALF, NODE_HALF);
    cudaEventRecord(evB, s2);
    cudaStreamWaitEvent(0, evB, 0);

    // Final aggregate over layer-2 buffers (no per-edge norm work at all)
    aggregate_kernel<false><<<gridA, TB>>>(h2_ptr, hf2_ptr, b1, out, 0, N_NODES);
}

// round 15
// speedup vs baseline: 1.3206x; 1.1230x over previous
#include <cuda_runtime.h>
#include <cuda_bf16.h>
#include <cuda_fp16.h>

#define N_NODES 50000
#define NODE_HALF 25000
#define E_EDGES 1600000
#define DIM     128
#define SLOTS   96      // max degree bucket capacity (Poisson(32): P(>96) ~ 1e-20)

// ---------------------------------------------------------------------------
// Scratch (device globals — no allocation allowed)
// All node features gathered/self-read in fp16. g_hf holds layer-1 h (scaled
// by dinv[row] via hfscale); g_hf2 holds layer-2 h (scaled in gemm epilogue).
// Dual buffers keep the agg1/gemm2 chunk pipeline race-free.
// ---------------------------------------------------------------------------
__device__ __half g_hf [N_NODES * DIM];       // layer-1 h * dinv (fp16)
__device__ __half g_hf2[N_NODES * DIM];       // layer-2 h * dinv (fp16)
__device__ float  g_x1 [N_NODES * DIM];       // layer-1 output (fp32, gemm2 input)
__device__ int    g_cnt [N_NODES];            // per-dst degree / insertion cursor
__device__ float  g_dinvf[N_NODES];           // rsqrt(deg+1)
__device__ int    g_psrc[N_NODES * SLOTS];    // padded bucket: src ids

// Pre-split weights, transposed to n-major: Wt[n][k], bf16 hi/lo
__device__ __nv_bfloat16 g_wt_hi[2][DIM * DIM];
__device__ __nv_bfloat16 g_wt_lo[2][DIM * DIM];

// ---------------------------------------------------------------------------
// Precompute
// ---------------------------------------------------------------------------
__global__ void zero_cnt_kernel() {
    int i = blockIdx.x * blockDim.x + threadIdx.x;
    if (i < N_NODES) g_cnt[i] = 0;
}

__global__ void bucket_kernel(const int* __restrict__ src, const int* __restrict__ dst) {
    int base = (blockIdx.x * blockDim.x + threadIdx.x) * 4;
    if (base < E_EDGES) {   // E divisible by 4
        int4 d4 = *(const int4*)(dst + base);
        int4 s4 = *(const int4*)(src + base);
        int p0 = atomicAdd(&g_cnt[d4.x], 1);
        int p1 = atomicAdd(&g_cnt[d4.y], 1);
        int p2 = atomicAdd(&g_cnt[d4.z], 1);
        int p3 = atomicAdd(&g_cnt[d4.w], 1);
        g_psrc[d4.x * SLOTS + p0] = s4.x;
        g_psrc[d4.y * SLOTS + p1] = s4.y;
        g_psrc[d4.z * SLOTS + p2] = s4.z;
        g_psrc[d4.w * SLOTS + p3] = s4.w;
    }
}

__global__ void dinv_kernel() {
    int i = blockIdx.x * blockDim.x + threadIdx.x;
    if (i < N_NODES) g_dinvf[i] = rsqrtf((float)(g_cnt[i] + 1));
}

// Coalesced rescale of g_hf by dinv[row] (runs after gemm1 + dinv; ~25MB L2)
__global__ void hfscale_kernel() {
    int i = blockIdx.x * blockDim.x + threadIdx.x;    // over N*16 uint4s
    if (i < N_NODES * (DIM / 8)) {
        int node = i >> 4;
        float dv = g_dinvf[node];
        uint4 r = ((const uint4*)g_hf)[i];
        unsigned* p = (unsigned*)&r;
        #pragma unroll
        for (int j = 0; j < 4; j++) {
            float2 f = __half22float2(*(__half2*)&p[j]);
            *(__half2*)&p[j] = __floats2half2_rn(f.x * dv, f.y * dv);
        }
        ((uint4*)g_hf)[i] = r;
    }
}

// ---------------------------------------------------------------------------
// Weight prep: split BOTH W (k-major [k][n]) into bf16 hi/lo, transposed [n][k]
// ---------------------------------------------------------------------------
__global__ void wsplit_kernel(const float* __restrict__ W0, const float* __restrict__ W1) {
    int t = blockIdx.x * blockDim.x + threadIdx.x;   // 2 * 16384
    if (t < 2 * DIM * DIM) {
        int which = t >> 14;
        int idx   = t & (DIM * DIM - 1);
        int k = idx >> 7, n = idx & 127;
        float v = (which ? W1 : W0)[idx];
        __nv_bfloat16 h = __float2bfloat16(v);
        __nv_bfloat16 l = __float2bfloat16(v - __bfloat162float(h));
        g_wt_hi[which][n * DIM + k] = h;
        g_wt_lo[which][n * DIM + k] = l;
    }
}

// ---------------------------------------------------------------------------
// Tensor-core GEMM: C[n,128] = A[n,128] @ W[128,128] in split-bf16
// fp16-only epilogue: Cf = half(C * rowscale[row])  (rowscale may be nullptr).
// ---------------------------------------------------------------------------
#define GBM  128
#define GBK  32
#define GPAD 40

__device__ __forceinline__ void mma16816(float* c, const unsigned* a, const unsigned* b) {
    asm volatile(
        "mma.sync.aligned.m16n8k16.row.col.f32.bf16.bf16.f32 "
        "{%0,%1,%2,%3}, {%4,%5,%6,%7}, {%8,%9}, {%0,%1,%2,%3};"
        : "+f"(c[0]), "+f"(c[1]), "+f"(c[2]), "+f"(c[3])
        : "r"(a[0]), "r"(a[1]), "r"(a[2]), "r"(a[3]), "r"(b[0]), "r"(b[1]));
}

__global__ __launch_bounds__(256) void gemm_tc_kernel(
    const float* __restrict__ A,
    const __nv_bfloat16* __restrict__ Wt_hi,
    const __nv_bfloat16* __restrict__ Wt_lo,
    __half* __restrict__ Cf,
    const float* __restrict__ rowscale, int n)
{
    __shared__ __nv_bfloat16 sAh[GBM][GPAD];
    __shared__ __nv_bfloat16 sAl[GBM][GPAD];
    __shared__ __nv_bfloat16 sWh[DIM][GPAD];
    __shared__ __nv_bfloat16 sWl[DIM][GPAD];

    const int tid   = threadIdx.x;
    const int lane  = tid & 31;
    const int w     = tid >> 5;
    const int wm    = w & 3;
    const int wn    = w >> 2;
    const int gq    = lane >> 2;
    const int gp    = lane & 3;
    const int row0  = blockIdx.x * GBM;

    float c[2][8][4];
    #pragma unroll
    for (int im = 0; im < 2; im++)
        #pragma unroll
        for (int j = 0; j < 8; j++)
            #pragma unroll
            for (int q = 0; q < 4; q++) c[im][j][q] = 0.f;

    for (int kc = 0; kc < DIM; kc += GBK) {
        #pragma unroll
        for (int i = 0; i < 8; i++) {
            int idx = tid + i * 256;
            int m   = idx >> 4;
            int k2  = (idx & 15) * 2;
            int row = row0 + m;
            float2 v = (row < n) ? *(const float2*)(A + (size_t)row * DIM + kc + k2)
                                 : make_float2(0.f, 0.f);
            __nv_bfloat16 hx = __float2bfloat16(v.x);
            __nv_bfloat16 hy = __float2bfloat16(v.y);
            __nv_bfloat16 lx = __float2bfloat16(v.x - __bfloat162float(hx));
            __nv_bfloat16 ly = __float2bfloat16(v.y - __bfloat162float(hy));
            __nv_bfloat162 ph; ph.x = hx; ph.y = hy;
            __nv_bfloat162 pl; pl.x = lx; pl.y = ly;
            *(__nv_bfloat162*)&sAh[m][k2] = ph;
            *(__nv_bfloat162*)&sAl[m][k2] = pl;
        }
        #pragma unroll
        for (int i = 0; i < 8; i++) {
            int idx = tid + i * 256;
            int nn  = idx >> 4;
            int kp  = (idx & 15) * 2;
            *(unsigned*)&sWh[nn][kp] = *(const unsigned*)(Wt_hi + nn * DIM + kc + kp);
            *(unsigned*)&sWl[nn][kp] = *(const unsigned*)(Wt_lo + nn * DIM + kc + kp);
        }
        __syncthreads();

        #pragma unroll
        for (int ks = 0; ks < 2; ks++) {
            const int kb = ks * 16;
            unsigned bh[8][2], bl[8][2];
            #pragma unroll
            for (int j = 0; j < 8; j++) {
                int nn = wn * 64 + j * 8 + gq;
                bh[j][0] = *(const unsigned*)&sWh[nn][kb + gp * 2];
                bh[j][1] = *(const unsigned*)&sWh[nn][kb + gp * 2 + 8];
                bl[j][0] = *(const unsigned*)&sWl[nn][kb + gp * 2];
                bl[j][1] = *(const unsigned*)&sWl[nn][kb + gp * 2 + 8];
            }
            #pragma unroll
            for (int im = 0; im < 2; im++) {
                int mr = wm * 32 + im * 16 + gq;
                unsigned ah[4], al[4];
                ah[0] = *(const unsigned*)&sAh[mr    ][kb + gp * 2];
                ah[1] = *(const unsigned*)&sAh[mr + 8][kb + gp * 2];
                ah[2] = *(const unsigned*)&sAh[mr    ][kb + gp * 2 + 8];
                ah[3] = *(const unsigned*)&sAh[mr + 8][kb + gp * 2 + 8];
                al[0] = *(const unsigned*)&sAl[mr    ][kb + gp * 2];
                al[1] = *(const unsigned*)&sAl[mr + 8][kb + gp * 2];
                al[2] = *(const unsigned*)&sAl[mr    ][kb + gp * 2 + 8];
                al[3] = *(const unsigned*)&sAl[mr + 8][kb + gp * 2 + 8];
                #pragma unroll
                for (int j = 0; j < 8; j++) {
                    mma16816(c[im][j], ah, bh[j]);
                    mma16816(c[im][j], ah, bl[j]);
                    mma16816(c[im][j], al, bh[j]);
                }
            }
        }
        __syncthreads();
    }

    #pragma unroll
    for (int im = 0; im < 2; im++) {
        int mr = row0 + wm * 32 + im * 16 + gq;
        float s0 = 1.f, s1 = 1.f;
        if (rowscale) {
            if (mr < n)     s0 = rowscale[mr];
            if (mr + 8 < n) s1 = rowscale[mr + 8];
        }
        #pragma unroll
        for (int j = 0; j < 8; j++) {
            int col = wn * 64 + j * 8 + gp * 2;
            if (mr < n)
                *(__half2*)(Cf + (size_t)mr * DIM + col) =
                    __floats2half2_rn(c[im][j][0] * s0, c[im][j][1] * s0);
            if (mr + 8 < n)
                *(__half2*)(Cf + (size_t)(mr + 8) * DIM + col) =
                    __floats2half2_rn(c[im][j][2] * s1, c[im][j][3] * s1);
        }
    }
}

// ---------------------------------------------------------------------------
// Fused aggregate: warp per node. hf rows are pre-scaled by dinv[row], so:
// out[d] = relu( dv * ( hf[d] + sum_e hf[src_e] ) + b )
// Per edge: 0.125 broadcast int4 LDG + 1 row gather.
// ---------------------------------------------------------------------------
__global__ __launch_bounds__(256) void aggregate_kernel(
    const __half* __restrict__ hf, const float* __restrict__ b,
    float* __restrict__ out, int node_base, int node_count)
{
    const int lane = threadIdx.x & 31;
    const int nrel = (blockIdx.x * blockDim.x + threadIdx.x) >> 5;
    if (nrel >= node_count) return;
    const int node = node_base + nrel;

    const int deg  = g_cnt[node];
    const float dv = g_dinvf[node];
    const int* sp  = g_psrc + node * SLOTS;

    // self term (row already scaled by dinv[node])
    uint2 sraw = *(const uint2*)(hf + (size_t)node * DIM + lane * 4);
    float2 s0 = __half22float2(*(__half2*)&sraw.x);
    float2 s1 = __half22float2(*(__half2*)&sraw.y);
    float4 es = make_float4(s0.x, s0.y, s1.x, s1.y);

    int e = 0;
    for (; e + 8 <= deg; e += 8) {
        int4 m0 = *(const int4*)(sp + e);       // 4 srcs per broadcast LDG
        int4 m1 = *(const int4*)(sp + e + 4);
        int s[8] = {m0.x, m0.y, m0.z, m0.w, m1.x, m1.y, m1.z, m1.w};
        uint2 raw[8];
        #pragma unroll
        for (int i = 0; i < 8; i++)
            raw[i] = *(const uint2*)(hf + (size_t)s[i] * DIM + lane * 4);
        #pragma unroll
        for (int i = 0; i < 8; i++) {
            float2 f0 = __half22float2(*(__half2*)&raw[i].x);
            float2 f1 = __half22float2(*(__half2*)&raw[i].y);
            es.x += f0.x; es.y += f0.y;
            es.z += f1.x; es.w += f1.y;
        }
    }
    for (; e < deg; e++) {
        int s = sp[e];
        uint2 raw = *(const uint2*)(hf + (size_t)s * DIM + lane * 4);
        float2 f0 = __half22float2(*(__half2*)&raw.x);
        float2 f1 = __half22float2(*(__half2*)&raw.y);
        es.x += f0.x; es.y += f0.y;
        es.z += f1.x; es.w += f1.y;
    }

    float4 b4 = *(const float4*)(b + lane * 4);
    es.x = fmaxf(es.x * dv + b4.x, 0.f);
    es.y = fmaxf(es.y * dv + b4.y, 0.f);
    es.z = fmaxf(es.z * dv + b4.z, 0.f);
    es.w = fmaxf(es.w * dv + b4.w, 0.f);
    *(float4*)(out + (size_t)node * DIM + lane * 4) = es;
}

// ---------------------------------------------------------------------------
// Launch: two-stream fork-join, hfscale bridge, 2-chunk agg1/gemm2 pipeline
// ---------------------------------------------------------------------------
extern "C" void kernel_launch(void* const* d_in, const int* in_sizes, int n_in,
                              void* d_out, int out_size)
{
    const float* x   = (const float*)d_in[0];
    const int*   ei  = (const int*)  d_in[1];
    const float* W0  = (const float*)d_in[2];
    const float* b0  = (const float*)d_in[3];
    const float* W1  = (const float*)d_in[4];
    const float* b1  = (const float*)d_in[5];
    float*       out = (float*)d_out;

    const int* src = ei;
    const int* dst = ei + E_EDGES;

    float *x1_ptr, *dinv_ptr;
    __half *hf_ptr, *hf2_ptr;
    __nv_bfloat16 *whi_ptr, *wlo_ptr;
    cudaGetSymbolAddress((void**)&hf_ptr,   g_hf);
    cudaGetSymbolAddress((void**)&hf2_ptr,  g_hf2);
    cudaGetSymbolAddress((void**)&x1_ptr,   g_x1);
    cudaGetSymbolAddress((void**)&dinv_ptr, g_dinvf);
    cudaGetSymbolAddress((void**)&whi_ptr,  g_wt_hi);
    cudaGetSymbolAddress((void**)&wlo_ptr,  g_wt_lo);

    const int TB = 256;
    const int gridN   = (N_NODES + TB - 1) / TB;
    const int gridE4  = (E_EDGES / 4 + TB - 1) / TB;
    const int gridG   = (N_NODES + GBM - 1) / GBM;
    const int gridGh  = (NODE_HALF + GBM - 1) / GBM;
    const int gridA   = (N_NODES * 32 + TB - 1) / TB;
    const int gridAh  = (NODE_HALF * 32 + TB - 1) / TB;
    const int gridW   = (2 * DIM * DIM + TB - 1) / TB;
    const int gridHS  = (N_NODES * (DIM / 8) + TB - 1) / TB;

    cudaStream_t s2;
    cudaStreamCreate(&s2);
    cudaEvent_t evF, evP, evG1, evHS, evB;
    cudaEventCreateWithFlags(&evF,  cudaEventDisableTiming);
    cudaEventCreateWithFlags(&evP,  cudaEventDisableTiming);
    cudaEventCreateWithFlags(&evG1, cudaEventDisableTiming);
    cudaEventCreateWithFlags(&evHS, cudaEventDisableTiming);
    cudaEventCreateWithFlags(&evB,  cudaEventDisableTiming);

    cudaEventRecord(evF, 0);
    cudaStreamWaitEvent(s2, evF, 0);

    // Stream 0: graph precompute (hidden under wsplit+gemm1 on s2)
    zero_cnt_kernel<<<gridN, TB>>>();
    bucket_kernel<<<gridE4, TB>>>(src, dst);
    dinv_kernel<<<gridN, TB>>>();
    cudaEventRecord(evP, 0);

    // Stream s2: weight split + layer-1 GEMM -> g_hf (unscaled yet)
    wsplit_kernel<<<gridW, TB, 0, s2>>>(W0, W1);
    gemm_tc_kernel<<<gridG, TB, 0, s2>>>(x, whi_ptr, wlo_ptr, hf_ptr, nullptr, N_NODES);
    cudaEventRecord(evG1, s2);

    // Stream 0: hfscale bridge (needs dinv [in-order] + gemm1)
    cudaStreamWaitEvent(0, evG1, 0);
    hfscale_kernel<<<gridHS, TB>>>();
    cudaEventRecord(evHS, 0);

    const __nv_bfloat16* w1h = whi_ptr + DIM * DIM;
    const __nv_bfloat16* w1l = wlo_ptr + DIM * DIM;

    // 2-chunk pipeline: agg1 reads g_hf (read-only now); gemm2 writes g_hf2
    // (disjoint, epilogue-scaled by dinv) -> race-free.
    cudaStreamWaitEvent(s2, evHS, 0);

    // chunk 0 on stream 0
    aggregate_kernel<<<gridAh, TB>>>(hf_ptr, b0, x1_ptr, 0, NODE_HALF);
    gemm_tc_kernel<<<gridGh, TB>>>(x1_ptr, w1h, w1l, hf2_ptr, dinv_ptr, NODE_HALF);

    // chunk 1 on stream s2
    aggregate_kernel<<<gridAh, TB, 0, s2>>>(hf_ptr, b0, x1_ptr, NODE_HALF, NODE_HALF);
    gemm_tc_kernel<<<gridGh, TB, 0, s2>>>(
        x1_ptr + (size_t)NODE_HALF * DIM, w1h, w1l,
        hf2_ptr + (size_t)NODE_HALF * DIM, dinv_ptr + NODE_HALF, NODE_HALF);
    cudaEventRecord(evB, s2);
    cudaStreamWaitEvent(0, evB, 0);

    // Final aggregate over layer-2 buffer (writes d_out)
    aggregate_kernel<<<gridA, TB>>>(hf2_ptr, b1, out, 0, N_NODES);
}

// round 17
// speedup vs baseline: 1.3400x; 1.0147x over previous
#include <cuda_runtime.h>
#include <cuda_bf16.h>
#include <cuda_fp16.h>

#define N_NODES 50000
#define NODE_HALF 25000
#define E_EDGES 1600000
#define DIM     128
#define SLOTS   96      // max degree bucket capacity (Poisson(32): P(>96) ~ 1e-20)

// ---------------------------------------------------------------------------
// Scratch (device globals — no allocation allowed)
// ---------------------------------------------------------------------------
__device__ __half g_hf [N_NODES * DIM];       // layer-1 h * dinv (fp16)
__device__ __half g_hf2[N_NODES * DIM];       // layer-2 h * dinv (fp16)
__device__ __half g_x1 [N_NODES * DIM];       // layer-1 output (fp16, gemm2 input)
__device__ int    g_cnt [N_NODES];            // per-dst degree / insertion cursor
__device__ float  g_dinvf[N_NODES];           // rsqrt(deg+1)
__device__ int    g_psrc[N_NODES * SLOTS];    // padded bucket: src ids

// Pre-split weights, transposed to n-major: Wt[n][k], bf16 hi/lo
__device__ __nv_bfloat16 g_wt_hi[2][DIM * DIM];
__device__ __nv_bfloat16 g_wt_lo[2][DIM * DIM];

// ---------------------------------------------------------------------------
// Precompute
// ---------------------------------------------------------------------------
__global__ void zero_cnt_kernel() {
    int i = blockIdx.x * blockDim.x + threadIdx.x;
    if (i < N_NODES) g_cnt[i] = 0;
}

__global__ void bucket_kernel(const int* __restrict__ src, const int* __restrict__ dst) {
    int base = (blockIdx.x * blockDim.x + threadIdx.x) * 4;
    if (base < E_EDGES) {   // E divisible by 4
        int4 d4 = *(const int4*)(dst + base);
        int4 s4 = *(const int4*)(src + base);
        int p0 = atomicAdd(&g_cnt[d4.x], 1);
        int p1 = atomicAdd(&g_cnt[d4.y], 1);
        int p2 = atomicAdd(&g_cnt[d4.z], 1);
        int p3 = atomicAdd(&g_cnt[d4.w], 1);
        g_psrc[d4.x * SLOTS + p0] = s4.x;
        g_psrc[d4.y * SLOTS + p1] = s4.y;
        g_psrc[d4.z * SLOTS + p2] = s4.z;
        g_psrc[d4.w * SLOTS + p3] = s4.w;
    }
}

__global__ void dinv_kernel() {
    int i = blockIdx.x * blockDim.x + threadIdx.x;
    if (i < N_NODES) g_dinvf[i] = rsqrtf((float)(g_cnt[i] + 1));
}

// Coalesced rescale of g_hf by dinv[row] (~25MB streaming through L2)
__global__ void hfscale_kernel() {
    int i = blockIdx.x * blockDim.x + threadIdx.x;    // over N*16 uint4s
    if (i < N_NODES * (DIM / 8)) {
        int node = i >> 4;
        float dv = g_dinvf[node];
        uint4 r = ((const uint4*)g_hf)[i];
        unsigned* p = (unsigned*)&r;
        #pragma unroll
        for (int j = 0; j < 4; j++) {
            float2 f = __half22float2(*(__half2*)&p[j]);
            *(__half2*)&p[j] = __floats2half2_rn(f.x * dv, f.y * dv);
        }
        ((uint4*)g_hf)[i] = r;
    }
}

// ---------------------------------------------------------------------------
// Weight prep: split BOTH W (k-major [k][n]) into bf16 hi/lo, transposed [n][k]
// ---------------------------------------------------------------------------
__global__ void wsplit_kernel(const float* __restrict__ W0, const float* __restrict__ W1) {
    int t = blockIdx.x * blockDim.x + threadIdx.x;   // 2 * 16384
    if (t < 2 * DIM * DIM) {
        int which = t >> 14;
        int idx   = t & (DIM * DIM - 1);
        int k = idx >> 7, n = idx & 127;
        float v = (which ? W1 : W0)[idx];
        __nv_bfloat16 h = __float2bfloat16(v);
        __nv_bfloat16 l = __float2bfloat16(v - __bfloat162float(h));
        g_wt_hi[which][n * DIM + k] = h;
        g_wt_lo[which][n * DIM + k] = l;
    }
}

// ---------------------------------------------------------------------------
// Tensor-core GEMM: C[n,128] = A[n,128] @ W[128,128] in split-bf16.
// A is fp32 (layer 1) or fp16 (layer 2, exact in hi/lo split).
// fp16 epilogue: Cf = half(C * rowscale[row])  (rowscale may be nullptr).
// ---------------------------------------------------------------------------
#define GBM  128
#define GBK  32
#define GPAD 40

__device__ __forceinline__ void mma16816(float* c, const unsigned* a, const unsigned* b) {
    asm volatile(
        "mma.sync.aligned.m16n8k16.row.col.f32.bf16.bf16.f32 "
        "{%0,%1,%2,%3}, {%4,%5,%6,%7}, {%8,%9}, {%0,%1,%2,%3};"
        : "+f"(c[0]), "+f"(c[1]), "+f"(c[2]), "+f"(c[3])
        : "r"(a[0]), "r"(a[1]), "r"(a[2]), "r"(a[3]), "r"(b[0]), "r"(b[1]));
}

template <bool AHALF>
__global__ __launch_bounds__(256) void gemm_tc_kernel(
    const void* __restrict__ Araw,
    const __nv_bfloat16* __restrict__ Wt_hi,
    const __nv_bfloat16* __restrict__ Wt_lo,
    __half* __restrict__ Cf,
    const float* __restrict__ rowscale, int n)
{
    __shared__ __nv_bfloat16 sAh[GBM][GPAD];
    __shared__ __nv_bfloat16 sAl[GBM][GPAD];
    __shared__ __nv_bfloat16 sWh[DIM][GPAD];
    __shared__ __nv_bfloat16 sWl[DIM][GPAD];

    const int tid   = threadIdx.x;
    const int lane  = tid & 31;
    const int w     = tid >> 5;
    const int wm    = w & 3;
    const int wn    = w >> 2;
    const int gq    = lane >> 2;
    const int gp    = lane & 3;
    const int row0  = blockIdx.x * GBM;

    float c[2][8][4];
    #pragma unroll
    for (int im = 0; im < 2; im++)
        #pragma unroll
        for (int j = 0; j < 8; j++)
            #pragma unroll
            for (int q = 0; q < 4; q++) c[im][j][q] = 0.f;

    for (int kc = 0; kc < DIM; kc += GBK) {
        #pragma unroll
        for (int i = 0; i < 8; i++) {
            int idx = tid + i * 256;
            int m   = idx >> 4;
            int k2  = (idx & 15) * 2;
            int row = row0 + m;
            float2 v = make_float2(0.f, 0.f);
            if (row < n) {
                if (AHALF) {
                    __half2 hv = *(const __half2*)((const __half*)Araw
                                    + (size_t)row * DIM + kc + k2);
                    v = __half22float2(hv);
                } else {
                    v = *(const float2*)((const float*)Araw
                                    + (size_t)row * DIM + kc + k2);
                }
            }
            __nv_bfloat16 hx = __float2bfloat16(v.x);
            __nv_bfloat16 hy = __float2bfloat16(v.y);
            __nv_bfloat16 lx = __float2bfloat16(v.x - __bfloat162float(hx));
            __nv_bfloat16 ly = __float2bfloat16(v.y - __bfloat162float(hy));
            __nv_bfloat162 ph; ph.x = hx; ph.y = hy;
            __nv_bfloat162 pl; pl.x = lx; pl.y = ly;
            *(__nv_bfloat162*)&sAh[m][k2] = ph;
            *(__nv_bfloat162*)&sAl[m][k2] = pl;
        }
        #pragma unroll
        for (int i = 0; i < 8; i++) {
            int idx = tid + i * 256;
            int nn  = idx >> 4;
            int kp  = (idx & 15) * 2;
            *(unsigned*)&sWh[nn][kp] = *(const unsigned*)(Wt_hi + nn * DIM + kc + kp);
            *(unsigned*)&sWl[nn][kp] = *(const unsigned*)(Wt_lo + nn * DIM + kc + kp);
        }
        __syncthreads();

        #pragma unroll
        for (int ks = 0; ks < 2; ks++) {
            const int kb = ks * 16;
            unsigned bh[8][2], bl[8][2];
            #pragma unroll
            for (int j = 0; j < 8; j++) {
                int nn = wn * 64 + j * 8 + gq;
                bh[j][0] = *(const unsigned*)&sWh[nn][kb + gp * 2];
                bh[j][1] = *(const unsigned*)&sWh[nn][kb + gp * 2 + 8];
                bl[j][0] = *(const unsigned*)&sWl[nn][kb + gp * 2];
                bl[j][1] = *(const unsigned*)&sWl[nn][kb + gp * 2 + 8];
            }
            #pragma unroll
            for (int im = 0; im < 2; im++) {
                int mr = wm * 32 + im * 16 + gq;
                unsigned ah[4], al[4];
                ah[0] = *(const unsigned*)&sAh[mr    ][kb + gp * 2];
                ah[1] = *(const unsigned*)&sAh[mr + 8][kb + gp * 2];
                ah[2] = *(const unsigned*)&sAh[mr    ][kb + gp * 2 + 8];
                ah[3] = *(const unsigned*)&sAh[mr + 8][kb + gp * 2 + 8];
                al[0] = *(const unsigned*)&sAl[mr    ][kb + gp * 2];
                al[1] = *(const unsigned*)&sAl[mr + 8][kb + gp * 2];
                al[2] = *(const unsigned*)&sAl[mr    ][kb + gp * 2 + 8];
                al[3] = *(const unsigned*)&sAl[mr + 8][kb + gp * 2 + 8];
                #pragma unroll
                for (int j = 0; j < 8; j++) {
                    mma16816(c[im][j], ah, bh[j]);
                    mma16816(c[im][j], ah, bl[j]);
                    mma16816(c[im][j], al, bh[j]);
                }
            }
        }
        __syncthreads();
    }

    #pragma unroll
    for (int im = 0; im < 2; im++) {
        int mr = row0 + wm * 32 + im * 16 + gq;
        float s0 = 1.f, s1 = 1.f;
        if (rowscale) {
            if (mr < n)     s0 = rowscale[mr];
            if (mr + 8 < n) s1 = rowscale[mr + 8];
        }
        #pragma unroll
        for (int j = 0; j < 8; j++) {
            int col = wn * 64 + j * 8 + gp * 2;
            if (mr < n)
                *(__half2*)(Cf + (size_t)mr * DIM + col) =
                    __floats2half2_rn(c[im][j][0] * s0, c[im][j][1] * s0);
            if (mr + 8 < n)
                *(__half2*)(Cf + (size_t)(mr + 8) * DIM + col) =
                    __floats2half2_rn(c[im][j][2] * s1, c[im][j][3] * s1);
        }
    }
}

// ---------------------------------------------------------------------------
// Fused aggregate: warp per node; hf rows pre-scaled by dinv[row].
// out[d] = relu( dv * ( hf[d] + sum_e hf[src_e] ) + b )
// OUT_HALF: x1 (fp16) for layer 1; else fp32 (d_out) for layer 2.
// ---------------------------------------------------------------------------
template <bool OUT_HALF>
__global__ __launch_bounds__(256) void aggregate_kernel(
    const __half* __restrict__ hf, const float* __restrict__ b,
    void* __restrict__ outraw, int node_base, int node_count)
{
    const int lane = threadIdx.x & 31;
    const int nrel = (blockIdx.x * blockDim.x + threadIdx.x) >> 5;
    if (nrel >= node_count) return;
    const int node = node_base + nrel;

    const int deg  = g_cnt[node];
    const float dv = g_dinvf[node];
    const int* sp  = g_psrc + node * SLOTS;

    // self term (row already scaled by dinv[node])
    uint2 sraw = *(const uint2*)(hf + (size_t)node * DIM + lane * 4);
    float2 sf0 = __half22float2(*(__half2*)&sraw.x);
    float2 sf1 = __half22float2(*(__half2*)&sraw.y);
    float4 es = make_float4(sf0.x, sf0.y, sf1.x, sf1.y);

    int e = 0;
    for (; e + 8 <= deg; e += 8) {
        int4 m0 = *(const int4*)(sp + e);       // 4 srcs per broadcast LDG
        int4 m1 = *(const int4*)(sp + e + 4);
        int s[8] = {m0.x, m0.y, m0.z, m0.w, m1.x, m1.y, m1.z, m1.w};
        uint2 raw[8];
        #pragma unroll
        for (int i = 0; i < 8; i++)
            raw[i] = *(const uint2*)(hf + (size_t)s[i] * DIM + lane * 4);
        #pragma unroll
        for (int i = 0; i < 8; i++) {
            float2 f0 = __half22float2(*(__half2*)&raw[i].x);
            float2 f1 = __half22float2(*(__half2*)&raw[i].y);
            es.x += f0.x; es.y += f0.y;
            es.z += f1.x; es.w += f1.y;
        }
    }
    for (; e < deg; e++) {
        int s = sp[e];
        uint2 raw = *(const uint2*)(hf + (size_t)s * DIM + lane * 4);
        float2 f0 = __half22float2(*(__half2*)&raw.x);
        float2 f1 = __half22float2(*(__half2*)&raw.y);
        es.x += f0.x; es.y += f0.y;
        es.z += f1.x; es.w += f1.y;
    }

    float4 b4 = *(const float4*)(b + lane * 4);
    es.x = fmaxf(es.x * dv + b4.x, 0.f);
    es.y = fmaxf(es.y * dv + b4.y, 0.f);
    es.z = fmaxf(es.z * dv + b4.z, 0.f);
    es.w = fmaxf(es.w * dv + b4.w, 0.f);

    if (OUT_HALF) {
        uint2 o;
        *(__half2*)&o.x = __floats2half2_rn(es.x, es.y);
        *(__half2*)&o.y = __floats2half2_rn(es.z, es.w);
        *(uint2*)((__half*)outraw + (size_t)node * DIM + lane * 4) = o;
    } else {
        *(float4*)((float*)outraw + (size_t)node * DIM + lane * 4) = es;
    }
}

// ---------------------------------------------------------------------------
// Launch: two-stream fork-join (proven teardown-clean topology), hfscale
// bridge, 2-chunk agg1/gemm2 pipeline (race-free via disjoint g_hf2)
// ---------------------------------------------------------------------------
extern "C" void kernel_launch(void* const* d_in, const int* in_sizes, int n_in,
                              void* d_out, int out_size)
{
    const float* x   = (const float*)d_in[0];
    const int*   ei  = (const int*)  d_in[1];
    const float* W0  = (const float*)d_in[2];
    const float* b0  = (const float*)d_in[3];
    const float* W1  = (const float*)d_in[4];
    const float* b1  = (const float*)d_in[5];
    float*       out = (float*)d_out;

    const int* src = ei;
    const int* dst = ei + E_EDGES;

    float *dinv_ptr;
    __half *hf_ptr, *hf2_ptr, *x1_ptr;
    __nv_bfloat16 *whi_ptr, *wlo_ptr;
    cudaGetSymbolAddress((void**)&hf_ptr,   g_hf);
    cudaGetSymbolAddress((void**)&hf2_ptr,  g_hf2);
    cudaGetSymbolAddress((void**)&x1_ptr,   g_x1);
    cudaGetSymbolAddress((void**)&dinv_ptr, g_dinvf);
    cudaGetSymbolAddress((void**)&whi_ptr,  g_wt_hi);
    cudaGetSymbolAddress((void**)&wlo_ptr,  g_wt_lo);

    const int TB = 256;
    const int gridN   = (N_NODES + TB - 1) / TB;
    const int gridE4  = (E_EDGES / 4 + TB - 1) / TB;
    const int gridG   = (N_NODES + GBM - 1) / GBM;
    const int gridGh  = (NODE_HALF + GBM - 1) / GBM;
    const int gridA   = (N_NODES * 32 + TB - 1) / TB;
    const int gridAh  = (NODE_HALF * 32 + TB - 1) / TB;
    const int gridW   = (2 * DIM * DIM + TB - 1) / TB;
    const int gridHS  = (N_NODES * (DIM / 8) + TB - 1) / TB;

    cudaStream_t s2;
    cudaStreamCreate(&s2);
    cudaEvent_t evF, evP, evG1, evHS, evB;
    cudaEventCreateWithFlags(&evF,  cudaEventDisableTiming);
    cudaEventCreateWithFlags(&evP,  cudaEventDisableTiming);
    cudaEventCreateWithFlags(&evG1, cudaEventDisableTiming);
    cudaEventCreateWithFlags(&evHS, cudaEventDisableTiming);
    cudaEventCreateWithFlags(&evB,  cudaEventDisableTiming);

    cudaEventRecord(evF, 0);
    cudaStreamWaitEvent(s2, evF, 0);

    // Stream 0: graph precompute (hidden under wsplit+gemm1 on s2)
    zero_cnt_kernel<<<gridN, TB>>>();
    bucket_kernel<<<gridE4, TB>>>(src, dst);
    dinv_kernel<<<gridN, TB>>>();
    cudaEventRecord(evP, 0);

    // Stream s2: weight split + layer-1 GEMM -> g_hf (unscaled yet)
    wsplit_kernel<<<gridW, TB, 0, s2>>>(W0, W1);
    gemm_tc_kernel<false><<<gridG, TB, 0, s2>>>(x, whi_ptr, wlo_ptr, hf_ptr,
                                                nullptr, N_NODES);
    cudaEventRecord(evG1, s2);

    // Stream 0: hfscale bridge (needs dinv [in-order] + gemm1)
    cudaStreamWaitEvent(0, evG1, 0);
    hfscale_kernel<<<gridHS, TB>>>();
    cudaEventRecord(evHS, 0);

    const __nv_bfloat16* w1h = whi_ptr + DIM * DIM;
    const __nv_bfloat16* w1l = wlo_ptr + DIM * DIM;

    // 2-chunk pipeline: agg1 reads g_hf (read-only now) -> x1 (fp16);
    // gemm2 reads x1, writes g_hf2 (disjoint, epilogue-scaled) -> race-free.
    cudaStreamWaitEvent(s2, evHS, 0);

    // chunk 0 on stream 0
    aggregate_kernel<true><<<gridAh, TB>>>(hf_ptr, b0, x1_ptr, 0, NODE_HALF);
    gemm_tc_kernel<true><<<gridGh, TB>>>(x1_ptr, w1h, w1l, hf2_ptr,
                                         dinv_ptr, NODE_HALF);

    // chunk 1 on stream s2
    aggregate_kernel<true><<<gridAh, TB, 0, s2>>>(hf_ptr, b0, x1_ptr,
                                                  NODE_HALF, NODE_HALF);
    gemm_tc_kernel<true><<<gridGh, TB, 0, s2>>>(
        x1_ptr + (size_t)NODE_HALF * DIM, w1h, w1l,
        hf2_ptr + (size_t)NODE_HALF * DIM, dinv_ptr + NODE_HALF, NODE_HALF);
    cudaEventRecord(evB, s2);
    cudaStreamWaitEvent(0, evB, 0);

    // Final aggregate over layer-2 buffer (writes fp32 d_out)
    aggregate_kernel<false><<<gridA, TB>>>(hf2_ptr, b1, out, 0, N_NODES);
}